// round 2
// baseline (speedup 1.0000x reference)
#include <cuda_runtime.h>

// StochasticPool2d: 2x2 stride-2 gumbel-max stochastic pooling.
// x:      [B=32, C=64, H=224, W=224] fp32
// gumbel: [B,C,112,112,4] fp32
// out:    [B,C,112,112] fp32
//
// HBM-roofline streaming kernel. One thread = 4 horizontally-adjacent output
// pixels: 8 front-batched LDG.128 (4 from x across the two window rows, 4 from
// gumbel) + 1 STG.128. Grid divides exactly (no tail branch), all index math
// 32-bit.

static constexpr int Hc = 224;
static constexpr int Wc = 224;
static constexpr int NH = 112;
static constexpr int NW = 112;
static constexpr int N_OUT   = 32 * 64 * NH * NW;   // 25,690,112
static constexpr int N_QUADS = N_OUT / 4;           // 6,422,528
static constexpr int QPR     = NW / 4;              // 28 quads per output row

__device__ __forceinline__ float pick4(float v0, float v1, float v2, float v3,
                                       float g0, float g1, float g2, float g3)
{
    // score_k = (v_k > 0 ? log(v_k) : log(1)=0) + gumbel_k ; first-max argmax
    float s0 = (v0 > 0.0f ? __logf(v0) : 0.0f) + g0;
    float s1 = (v1 > 0.0f ? __logf(v1) : 0.0f) + g1;
    float s2 = (v2 > 0.0f ? __logf(v2) : 0.0f) + g2;
    float s3 = (v3 > 0.0f ? __logf(v3) : 0.0f) + g3;

    float best_s = s0;
    float best_v = v0;
    if (s1 > best_s) { best_s = s1; best_v = v1; }
    if (s2 > best_s) { best_s = s2; best_v = v2; }
    if (s3 > best_s) { best_s = s3; best_v = v3; }
    return best_v;
}

__global__ void __launch_bounds__(256)
stochastic_pool2d_kernel(const float* __restrict__ x,
                         const float* __restrict__ gum,
                         float* __restrict__ out)
{
    int t = blockIdx.x * blockDim.x + threadIdx.x;   // quad index, always < N_QUADS

    // t -> (bc, i, jq). jq covers output cols [4*jq, 4*jq+3].
    int jq = t % QPR;
    int r  = t / QPR;
    int i  = r % NH;
    int bc = r / NH;          // fused B*C index, < 2048

    // x: two input rows (2i, 2i+1), 8 consecutive floats each, starting col 8*jq.
    const float* xrow = x + (size_t)bc * (Hc * Wc) + (2 * i) * Wc + 8 * jq;
    float4 xa0 = *reinterpret_cast<const float4*>(xrow);           // row 2i, cols 0..3
    float4 xa1 = *reinterpret_cast<const float4*>(xrow + 4);       // row 2i, cols 4..7
    float4 xb0 = *reinterpret_cast<const float4*>(xrow + Wc);      // row 2i+1
    float4 xb1 = *reinterpret_cast<const float4*>(xrow + Wc + 4);

    // gumbel: [.., i, j, 4] — 4 pixels = 16 contiguous floats.
    const float* gp = gum + ((size_t)bc * (NH * NW) + i * NW + 4 * jq) * 4;
    float4 g0 = *reinterpret_cast<const float4*>(gp);
    float4 g1 = *reinterpret_cast<const float4*>(gp + 4);
    float4 g2 = *reinterpret_cast<const float4*>(gp + 8);
    float4 g3 = *reinterpret_cast<const float4*>(gp + 12);

    // Window flatten order k = di*2 + dj (row-major within 2x2).
    float4 o;
    o.x = pick4(xa0.x, xa0.y, xb0.x, xb0.y, g0.x, g0.y, g0.z, g0.w); // pixel 4*jq
    o.y = pick4(xa0.z, xa0.w, xb0.z, xb0.w, g1.x, g1.y, g1.z, g1.w); // pixel 4*jq+1
    o.z = pick4(xa1.x, xa1.y, xb1.x, xb1.y, g2.x, g2.y, g2.z, g2.w); // pixel 4*jq+2
    o.w = pick4(xa1.z, xa1.w, xb1.z, xb1.w, g3.x, g3.y, g3.z, g3.w); // pixel 4*jq+3

    float* op = out + (size_t)bc * (NH * NW) + i * NW + 4 * jq;
    *reinterpret_cast<float4*>(op) = o;
}

extern "C" void kernel_launch(void* const* d_in, const int* in_sizes, int n_in,
                              void* d_out, int out_size)
{
    const float* x   = (const float*)d_in[0];
    const float* gum = (const float*)d_in[1];
    float* out = (float*)d_out;

    const int threads = 256;
    const int blocks  = N_QUADS / threads;   // 25,088 exactly
    stochastic_pool2d_kernel<<<blocks, threads>>>(x, gum, out);
}

// round 3
// speedup vs baseline: 1.0238x; 1.0238x over previous
#include <cuda_runtime.h>

// StochasticPool2d: 2x2 stride-2 gumbel-max stochastic pooling.
// x:      [B=32, C=64, H=224, W=224] fp32
// gumbel: [B,C,112,112,4] fp32
// out:    [B,C,112,112] fp32
//
// HBM-roofline streaming kernel (R1 shape: 2 output pixels/thread, 32 regs,
// high occupancy) + streaming cache hints: every byte is single-touch, so all
// loads are __ldcs (evict-first) and the store is __stcs.

static constexpr int Hc = 224;
static constexpr int Wc = 224;
static constexpr int NH = 112;
static constexpr int NW = 112;
static constexpr int N_OUT   = 32 * 64 * NH * NW;   // 25,690,112
static constexpr int N_PAIRS = N_OUT / 2;           // 12,845,056
static constexpr int PPR     = NW / 2;              // 56 pairs per output row

__device__ __forceinline__ float pick4(float v0, float v1, float v2, float v3,
                                       float g0, float g1, float g2, float g3)
{
    // score_k = (v_k > 0 ? log(v_k) : log(1)=0) + gumbel_k ; first-max argmax
    float s0 = (v0 > 0.0f ? __logf(v0) : 0.0f) + g0;
    float s1 = (v1 > 0.0f ? __logf(v1) : 0.0f) + g1;
    float s2 = (v2 > 0.0f ? __logf(v2) : 0.0f) + g2;
    float s3 = (v3 > 0.0f ? __logf(v3) : 0.0f) + g3;

    float best_s = s0;
    float best_v = v0;
    if (s1 > best_s) { best_s = s1; best_v = v1; }
    if (s2 > best_s) { best_s = s2; best_v = v2; }
    if (s3 > best_s) { best_s = s3; best_v = v3; }
    return best_v;
}

__global__ void __launch_bounds__(256)
stochastic_pool2d_kernel(const float* __restrict__ x,
                         const float* __restrict__ gum,
                         float* __restrict__ out)
{
    int t = blockIdx.x * blockDim.x + threadIdx.x;   // pair index, always < N_PAIRS

    // t -> (bc, i, jp). jp covers output cols [2*jp, 2*jp+1].
    int jp = t % PPR;
    int r  = t / PPR;
    int i  = r % NH;
    int bc = r / NH;          // fused B*C index, < 2048

    // x: two input rows (2i, 2i+1), 4 consecutive floats each, starting col 4*jp.
    const float* xrow = x + (size_t)bc * (Hc * Wc) + (2 * i) * Wc + 4 * jp;
    float4 x0 = __ldcs(reinterpret_cast<const float4*>(xrow));        // row 2i
    float4 x1 = __ldcs(reinterpret_cast<const float4*>(xrow + Wc));   // row 2i+1

    // gumbel: [.., i, j, 4] — 2 pixels = 8 contiguous floats, 32B aligned.
    const float* gp = gum + ((size_t)bc * (NH * NW) + i * NW + 2 * jp) * 4;
    float4 g0 = __ldcs(reinterpret_cast<const float4*>(gp));
    float4 g1 = __ldcs(reinterpret_cast<const float4*>(gp + 4));

    // Window flatten order k = di*2 + dj (row-major within 2x2).
    float2 o;
    o.x = pick4(x0.x, x0.y, x1.x, x1.y, g0.x, g0.y, g0.z, g0.w); // pixel 2*jp
    o.y = pick4(x0.z, x0.w, x1.z, x1.w, g1.x, g1.y, g1.z, g1.w); // pixel 2*jp+1

    float* op = out + (size_t)bc * (NH * NW) + i * NW + 2 * jp;
    __stcs(reinterpret_cast<float2*>(op), o);
}

extern "C" void kernel_launch(void* const* d_in, const int* in_sizes, int n_in,
                              void* d_out, int out_size)
{
    const float* x   = (const float*)d_in[0];
    const float* gum = (const float*)d_in[1];
    float* out = (float*)d_out;

    const int threads = 256;
    const int blocks  = N_PAIRS / threads;   // 50,176 exactly
    stochastic_pool2d_kernel<<<blocks, threads>>>(x, gum, out);
}